// round 9
// baseline (speedup 1.0000x reference)
#include <cuda_runtime.h>
#include <cuda_bf16.h>
#include <cstdint>

#define N_NODES 50000
#define NPAD    50048      // 782 * 64
#define CH      128

// ---------------------------------------------------------------------------
// Scratch (device globals -- no allocation allowed)
// ---------------------------------------------------------------------------
__device__ __align__(16) float g_agg[(size_t)N_NODES * CH];
__device__ __align__(16) float g_h1[(size_t)N_NODES * CH];
__device__ float g_deg[N_NODES];
__device__ int   g_is64;

// bf16 hi/lo operand staging
__device__ __align__(16) __nv_bfloat16 g_Ahi[(size_t)NPAD * CH];  // scaled agg
__device__ __align__(16) __nv_bfloat16 g_Alo[(size_t)NPAD * CH];
__device__ __align__(16) __nv_bfloat16 g_Xhi[(size_t)NPAD * CH];  // x, then h2
__device__ __align__(16) __nv_bfloat16 g_Xlo[(size_t)NPAD * CH];
__device__ __align__(16) __nv_bfloat16 g_H1hi[(size_t)NPAD * CH]; // h1
__device__ __align__(16) __nv_bfloat16 g_H1lo[(size_t)NPAD * CH];

// transposed weights Bt[n][k] (k contiguous): layer1/2 K=256, decoder K=128
__device__ __align__(16) __nv_bfloat16 g_W1t_hi[128 * 256];
__device__ __align__(16) __nv_bfloat16 g_W1t_lo[128 * 256];
__device__ __align__(16) __nv_bfloat16 g_W2t_hi[128 * 256];
__device__ __align__(16) __nv_bfloat16 g_W2t_lo[128 * 256];
__device__ __align__(16) __nv_bfloat16 g_Wdt_hi[128 * 128];
__device__ __align__(16) __nv_bfloat16 g_Wdt_lo[128 * 128];

__device__ __forceinline__ void bfsplit(float v, __nv_bfloat16& h, __nv_bfloat16& l) {
    h = __float2bfloat16(v);
    l = __float2bfloat16(v - __bfloat162float(h));
}

// ---------------------------------------------------------------------------
// detect: is the edge buffer int64 or int32?
// ---------------------------------------------------------------------------
__global__ void detect_kernel(const unsigned* __restrict__ e) {
    __shared__ unsigned red[256];
    unsigned acc = 0;
    int t = threadIdx.x;
    #pragma unroll
    for (int j = 0; j < 8; j++) acc |= e[(t * 8 + j) * 2 + 1];
    red[t] = acc;
    __syncthreads();
    for (int s = 128; s > 0; s >>= 1) {
        if (t < s) red[t] |= red[t + s];
        __syncthreads();
    }
    if (t == 0) g_is64 = (red[0] == 0) ? 1 : 0;
}

// ---------------------------------------------------------------------------
// prep_w: transpose + bf16-split all weights once. 81920 elements total.
// ---------------------------------------------------------------------------
__global__ void prep_w_kernel(const float* __restrict__ W1l,
                              const float* __restrict__ W1r,
                              const float* __restrict__ W2l,
                              const float* __restrict__ W2r,
                              const float* __restrict__ Wd) {
    int idx = blockIdx.x * blockDim.x + threadIdx.x;
    if (idx < 32768) {
        int nn = idx >> 8, k = idx & 255;
        float v = (k < 128) ? W1l[(size_t)k * CH + nn]
                            : W1r[(size_t)(k - 128) * CH + nn];
        bfsplit(v, g_W1t_hi[nn * 256 + k], g_W1t_lo[nn * 256 + k]);
    } else if (idx < 65536) {
        int r = idx - 32768;
        int nn = r >> 8, k = r & 255;
        float v = (k < 128) ? W2l[(size_t)k * CH + nn]
                            : W2r[(size_t)(k - 128) * CH + nn];
        bfsplit(v, g_W2t_hi[nn * 256 + k], g_W2t_lo[nn * 256 + k]);
    } else if (idx < 81920) {
        int r = idx - 65536;
        int nn = r >> 7, k = r & 127;
        float v = Wd[(size_t)k * CH + nn];
        bfsplit(v, g_Wdt_hi[nn * 128 + k], g_Wdt_lo[nn * 128 + k]);
    }
}

// ---------------------------------------------------------------------------
// convert: fp32 -> bf16 hi/lo. mode 0: src=x -> g_Xhi/lo (no scale).
//          mode 1: g_agg -> g_Ahi/lo, scaled by 1/max(deg,1).
// Covers NPAD rows; pad rows written as zero.
// ---------------------------------------------------------------------------
__global__ void convert_kernel(const float* __restrict__ src, int n, int mode) {
    int i = blockIdx.x * blockDim.x + threadIdx.x;   // [0, NPAD*32)
    if (i >= NPAD * 32) return;
    int row = i >> 5;
    int seg = i & 31;
    const float* s = mode ? g_agg : src;
    float4 v = make_float4(0.f, 0.f, 0.f, 0.f);
    if (row < n) {
        v = *(const float4*)(s + (size_t)row * CH + seg * 4);
        if (mode) {
            float sc = 1.0f / fmaxf(g_deg[row], 1.0f);
            v.x *= sc; v.y *= sc; v.z *= sc; v.w *= sc;
        }
    }
    __nv_bfloat162 h01, h23, l01, l23;
    bfsplit(v.x, h01.x, l01.x);  bfsplit(v.y, h01.y, l01.y);
    bfsplit(v.z, h23.x, l23.x);  bfsplit(v.w, h23.y, l23.y);
    size_t o = (size_t)row * CH + seg * 4;
    __nv_bfloat16* dh = mode ? g_Ahi : g_Xhi;
    __nv_bfloat16* dl = mode ? g_Alo : g_Xlo;
    *(uint2*)(dh + o) = make_uint2(*(uint32_t*)&h01, *(uint32_t*)&h23);
    *(uint2*)(dl + o) = make_uint2(*(uint32_t*)&l01, *(uint32_t*)&l23);
}

// ---------------------------------------------------------------------------
// clear: zero g_agg (and optionally g_deg)
// ---------------------------------------------------------------------------
__global__ void clear_kernel(int with_deg) {
    int i = blockIdx.x * blockDim.x + threadIdx.x;
    int total = N_NODES * CH / 4;
    if (i < total) ((float4*)g_agg)[i] = make_float4(0.f, 0.f, 0.f, 0.f);
    if (with_deg && i < N_NODES) g_deg[i] = 0.f;
}

// ---------------------------------------------------------------------------
// scatter: one warp per edge, vector RED (at LTS floor)
// ---------------------------------------------------------------------------
template <bool FIRST>
__global__ void scatter_kernel(const float* __restrict__ feat_ext,
                               const void* __restrict__ edge_raw,
                               int E) {
    int gw = (blockIdx.x * blockDim.x + threadIdx.x) >> 5;
    int lane = threadIdx.x & 31;
    if (gw >= E) return;

    const float* __restrict__ feat = FIRST ? feat_ext : g_h1;

    int s, d;
    if (g_is64) {
        const long long* e = (const long long*)edge_raw;
        s = (int)e[gw];
        d = (int)e[E + gw];
    } else {
        const int* e = (const int*)edge_raw;
        s = e[gw];
        d = e[E + gw];
    }
    if ((unsigned)s >= N_NODES || (unsigned)d >= N_NODES) return;

    float4 v = ((const float4*)(feat + (size_t)s * CH))[lane];
    float* out = g_agg + (size_t)d * CH + lane * 4;
    asm volatile("red.global.add.v4.f32 [%0], {%1,%2,%3,%4};"
                 :: "l"(out), "f"(v.x), "f"(v.y), "f"(v.z), "f"(v.w)
                 : "memory");
    if (FIRST && lane == 0) atomicAdd(g_deg + d, 1.0f);
}

// ---------------------------------------------------------------------------
// GEMM via mma.sync m16n8k16 bf16, bf16x3 split, all operands pre-converted.
// BM=64, BN=128, KC=32. 8 warps in 2(M) x 4(N); warp tile 32x32.
// MODE 1: A=[agg|x],  B=g_W1t, relu+b1 -> g_h1 (fp32) + g_H1hi/lo
// MODE 2: A=[agg|h1], B=g_W2t, relu+b2 -> g_Xhi/lo (h2, bf16 only)
// MODE 3: A=h2(g_X),  B=g_Wdt, alpha*(.+bd)+(1-a)*x -> out_ext
// ---------------------------------------------------------------------------
#define BM 64
#define KC 32
#define ASTR 40

__device__ __forceinline__ void mma_bf16(float* d, const uint32_t* a,
                                         const uint32_t* b) {
    asm volatile(
        "mma.sync.aligned.m16n8k16.row.col.f32.bf16.bf16.f32 "
        "{%0,%1,%2,%3}, {%4,%5,%6,%7}, {%8,%9}, {%0,%1,%2,%3};"
        : "+f"(d[0]), "+f"(d[1]), "+f"(d[2]), "+f"(d[3])
        : "r"(a[0]), "r"(a[1]), "r"(a[2]), "r"(a[3]), "r"(b[0]), "r"(b[1]));
}

template <int MODE>
__global__ __launch_bounds__(256) void gemm_kernel(
    const float* __restrict__ bias,
    const float* __restrict__ xres,    // MODE 3
    const float* __restrict__ alpha_p, // MODE 3
    float* __restrict__ out_ext,       // MODE 3
    int n)
{
    __shared__ __nv_bfloat16 Ahi[BM][ASTR];
    __shared__ __nv_bfloat16 Alo[BM][ASTR];
    __shared__ __nv_bfloat16 Bhi[128][ASTR];
    __shared__ __nv_bfloat16 Blo[128][ASTR];
    __shared__ float s_bias[128];

    int t = threadIdx.x;
    int lane = t & 31;
    int w = t >> 5;
    int wm = w >> 2;
    int wn = w & 3;
    int block_row = blockIdx.x * BM;

    if (t < 128) s_bias[t] = bias[t];

    float acc[2][4][4];
    #pragma unroll
    for (int mi = 0; mi < 2; mi++)
        #pragma unroll
        for (int nj = 0; nj < 4; nj++)
            #pragma unroll
            for (int q = 0; q < 4; q++) acc[mi][nj][q] = 0.f;

    const int NCH = (MODE == 3) ? 4 : 8;
    const int KB  = (MODE == 3) ? 128 : 256;

    #pragma unroll 1
    for (int c = 0; c < NCH; c++) {
        const __nv_bfloat16 *ah, *al, *bh, *bl;
        if (MODE == 3)      { ah = g_Xhi;  al = g_Xlo; }
        else if (c < 4)     { ah = g_Ahi;  al = g_Alo; }
        else if (MODE == 1) { ah = g_Xhi;  al = g_Xlo; }
        else                { ah = g_H1hi; al = g_H1lo; }
        if (MODE == 1)      { bh = g_W1t_hi; bl = g_W1t_lo; }
        else if (MODE == 2) { bh = g_W2t_hi; bl = g_W2t_lo; }
        else                { bh = g_Wdt_hi; bl = g_Wdt_lo; }
        int kofsA = (c & 3) * KC;
        int kofsB = c * KC;

        __syncthreads();   // previous chunk's mma reads done before restage

        // ---- stage A: straight bf16 copy, 64 rows x 32 k ----
        {
            int row = t >> 2;
            int q = t & 3;
            size_t go = (size_t)(block_row + row) * CH + kofsA + q * 8;
            *(uint4*)&Ahi[row][q * 8] = *(const uint4*)(ah + go);
            *(uint4*)&Alo[row][q * 8] = *(const uint4*)(al + go);
        }
        // ---- stage B: straight bf16 copy, 128 rows x 32 k ----
        {
            int nn = t >> 1;
            int hf = (t & 1) * 16;
            size_t go = (size_t)nn * KB + kofsB + hf;
            *(uint4*)&Bhi[nn][hf]     = *(const uint4*)(bh + go);
            *(uint4*)&Bhi[nn][hf + 8] = *(const uint4*)(bh + go + 8);
            *(uint4*)&Blo[nn][hf]     = *(const uint4*)(bl + go);
            *(uint4*)&Blo[nn][hf + 8] = *(const uint4*)(bl + go + 8);
        }
        __syncthreads();

        // ---- mma: 2 k16-steps, 3 passes each (identical to proven R8) ----
        #pragma unroll
        for (int kk = 0; kk < KC; kk += 16) {
            int kw = kk + (lane & 3) * 2;
            int rr = wm * 32 + (lane >> 2);
            uint32_t a_hi[2][4], a_lo[2][4], b_hi[4][2], b_lo[4][2];
            #pragma unroll
            for (int mi = 0; mi < 2; mi++) {
                int r = rr + mi * 16;
                a_hi[mi][0] = *(uint32_t*)&Ahi[r][kw];
                a_hi[mi][1] = *(uint32_t*)&Ahi[r + 8][kw];
                a_hi[mi][2] = *(uint32_t*)&Ahi[r][kw + 8];
                a_hi[mi][3] = *(uint32_t*)&Ahi[r + 8][kw + 8];
                a_lo[mi][0] = *(uint32_t*)&Alo[r][kw];
                a_lo[mi][1] = *(uint32_t*)&Alo[r + 8][kw];
                a_lo[mi][2] = *(uint32_t*)&Alo[r][kw + 8];
                a_lo[mi][3] = *(uint32_t*)&Alo[r + 8][kw + 8];
            }
            #pragma unroll
            for (int nj = 0; nj < 4; nj++) {
                int cn = wn * 32 + nj * 8 + (lane >> 2);
                b_hi[nj][0] = *(uint32_t*)&Bhi[cn][kw];
                b_hi[nj][1] = *(uint32_t*)&Bhi[cn][kw + 8];
                b_lo[nj][0] = *(uint32_t*)&Blo[cn][kw];
                b_lo[nj][1] = *(uint32_t*)&Blo[cn][kw + 8];
            }
            #pragma unroll
            for (int mi = 0; mi < 2; mi++)
                #pragma unroll
                for (int nj = 0; nj < 4; nj++) {
                    mma_bf16(acc[mi][nj], a_hi[mi], b_hi[nj]);
                    mma_bf16(acc[mi][nj], a_hi[mi], b_lo[nj]);
                    mma_bf16(acc[mi][nj], a_lo[mi], b_hi[nj]);
                }
        }
    }

    // ---- epilogue ----
    float alpha = 0.f, one_m = 0.f;
    if (MODE == 3) { alpha = *alpha_p; one_m = 1.0f - alpha; }

    #pragma unroll
    for (int mi = 0; mi < 2; mi++) {
        #pragma unroll
        for (int part = 0; part < 2; part++) {
            int grow = block_row + wm * 32 + mi * 16 + part * 8 + (lane >> 2);
            if (grow < n) {
                #pragma unroll
                for (int nj = 0; nj < 4; nj++) {
                    int gcol = wn * 32 + nj * 8 + (lane & 3) * 2;
                    float v0 = acc[mi][nj][part * 2 + 0] + s_bias[gcol];
                    float v1 = acc[mi][nj][part * 2 + 1] + s_bias[gcol + 1];
                    size_t o = (size_t)grow * CH + gcol;
                    if (MODE == 3) {
                        float2 xv = *(const float2*)(xres + o);
                        float2 ov;
                        ov.x = alpha * v0 + one_m * xv.x;
                        ov.y = alpha * v1 + one_m * xv.y;
                        *(float2*)(out_ext + o) = ov;
                    } else {
                        v0 = fmaxf(v0, 0.f);
                        v1 = fmaxf(v1, 0.f);
                        __nv_bfloat162 h, l;
                        bfsplit(v0, h.x, l.x);
                        bfsplit(v1, h.y, l.y);
                        if (MODE == 1) {
                            *(float2*)(g_h1 + o) = make_float2(v0, v1);
                            *(__nv_bfloat162*)(g_H1hi + o) = h;
                            *(__nv_bfloat162*)(g_H1lo + o) = l;
                        } else {  // MODE 2: h2 consumed only by decoder
                            *(__nv_bfloat162*)(g_Xhi + o) = h;
                            *(__nv_bfloat162*)(g_Xlo + o) = l;
                        }
                    }
                }
            }
        }
    }
}

// ---------------------------------------------------------------------------
extern "C" void kernel_launch(void* const* d_in, const int* in_sizes, int n_in,
                              void* d_out, int out_size) {
    const float* x     = (const float*)d_in[0];
    const void*  edge  = d_in[1];
    const float* W1_l  = (const float*)d_in[2];
    const float* b1    = (const float*)d_in[3];
    const float* W1_r  = (const float*)d_in[4];
    const float* W2_l  = (const float*)d_in[5];
    const float* b2    = (const float*)d_in[6];
    const float* W2_r  = (const float*)d_in[7];
    const float* Wd    = (const float*)d_in[8];
    const float* bd    = (const float*)d_in[9];
    const float* alpha = (const float*)d_in[10];
    float* out = (float*)d_out;

    int n = in_sizes[0] / CH;            // 50000
    int E = in_sizes[1] / 2;             // 640000

    int clear_blocks = (N_NODES * CH / 4 + 255) / 256;
    int conv_blocks  = (NPAD * 32 + 255) / 256;
    int scat_blocks  = (E + 7) / 8;
    int gemm_blocks  = NPAD / BM;        // 782

    detect_kernel<<<1, 256>>>((const unsigned*)edge);
    prep_w_kernel<<<320, 256>>>(W1_l, W1_r, W2_l, W2_r, Wd);
    convert_kernel<<<conv_blocks, 256>>>(x, n, 0);     // x -> g_Xhi/lo

    // Layer 1
    clear_kernel<<<clear_blocks, 256>>>(1);
    scatter_kernel<true><<<scat_blocks, 256>>>(x, edge, E);
    convert_kernel<<<conv_blocks, 256>>>(nullptr, n, 1);  // agg -> g_Ahi/lo
    gemm_kernel<1><<<gemm_blocks, 256>>>(b1, nullptr, nullptr, nullptr, n);

    // Layer 2
    clear_kernel<<<clear_blocks, 256>>>(0);
    scatter_kernel<false><<<scat_blocks, 256>>>(nullptr, edge, E);
    convert_kernel<<<conv_blocks, 256>>>(nullptr, n, 1);
    gemm_kernel<2><<<gemm_blocks, 256>>>(b2, nullptr, nullptr, nullptr, n);

    // Decoder + residual
    gemm_kernel<3><<<gemm_blocks, 256>>>(bd, x, alpha, out, n);
}

// round 10
// speedup vs baseline: 1.1369x; 1.1369x over previous
#include <cuda_runtime.h>
#include <cuda_bf16.h>
#include <cstdint>

#define N_NODES 50000
#define CH 128

// Scratch (device globals -- no allocation allowed)
__device__ __align__(16) float g_agg[(size_t)N_NODES * CH];
__device__ __align__(16) float g_agg2[(size_t)N_NODES * CH];
__device__ __align__(16) float g_h1[(size_t)N_NODES * CH];
__device__ float g_deg[N_NODES];
__device__ int   g_is64;

// ---------------------------------------------------------------------------
// detect: is the edge buffer int64 or int32?
// ---------------------------------------------------------------------------
__global__ void detect_kernel(const unsigned* __restrict__ e) {
    __shared__ unsigned red[256];
    unsigned acc = 0;
    int t = threadIdx.x;
    #pragma unroll
    for (int j = 0; j < 8; j++) acc |= e[(t * 8 + j) * 2 + 1];
    red[t] = acc;
    __syncthreads();
    for (int s = 128; s > 0; s >>= 1) {
        if (t < s) red[t] |= red[t + s];
        __syncthreads();
    }
    if (t == 0) g_is64 = (red[0] == 0) ? 1 : 0;
}

// ---------------------------------------------------------------------------
// clear: zero g_agg, g_agg2, g_deg in one pass
// ---------------------------------------------------------------------------
__global__ void clear_kernel() {
    int i = blockIdx.x * blockDim.x + threadIdx.x;
    int total = N_NODES * CH / 4;
    if (i < total) {
        ((float4*)g_agg)[i]  = make_float4(0.f, 0.f, 0.f, 0.f);
        ((float4*)g_agg2)[i] = make_float4(0.f, 0.f, 0.f, 0.f);
    }
    if (i < N_NODES) g_deg[i] = 0.f;
}

// ---------------------------------------------------------------------------
// scatter: one warp per edge, vector RED (at LTS floor). TGT: 0 -> g_agg
// (reads feat_ext, counts degree), 1 -> g_agg2 (reads g_h1).
// ---------------------------------------------------------------------------
template <int TGT>
__global__ void scatter_kernel(const float* __restrict__ feat_ext,
                               const void* __restrict__ edge_raw,
                               int E) {
    int gw = (blockIdx.x * blockDim.x + threadIdx.x) >> 5;
    int lane = threadIdx.x & 31;
    if (gw >= E) return;

    const float* __restrict__ feat = (TGT == 0) ? feat_ext : g_h1;
    float* __restrict__ aggp = (TGT == 0) ? g_agg : g_agg2;

    int s, d;
    if (g_is64) {
        const long long* e = (const long long*)edge_raw;
        s = (int)e[gw];
        d = (int)e[E + gw];
    } else {
        const int* e = (const int*)edge_raw;
        s = e[gw];
        d = e[E + gw];
    }
    if ((unsigned)s >= N_NODES || (unsigned)d >= N_NODES) return;

    float4 v = ((const float4*)(feat + (size_t)s * CH))[lane];
    float* out = aggp + (size_t)d * CH + lane * 4;
    asm volatile("red.global.add.v4.f32 [%0], {%1,%2,%3,%4};"
                 :: "l"(out), "f"(v.x), "f"(v.y), "f"(v.z), "f"(v.w)
                 : "memory");
    if (TGT == 0 && lane == 0) atomicAdd(g_deg + d, 1.0f);
}

// ---------------------------------------------------------------------------
// GEMM via mma.sync m16n8k16 bf16 (HMMA), bf16x3 error-compensated split,
// with register-prefetch software pipeline (chunk c+1 LDG overlaps chunk c mma).
// BM=64, BN=128, KC=32. 8 warps in 2(M) x 4(N); warp tile 32x32.
// MODE 1: relu( [agg/deg  | x ] @ [W1_l;W1_r] + b1 ) -> g_h1
// MODE 2: relu( [agg2/deg | h1] @ [W2_l;W2_r] + b2 ) -> g_agg (h2)
// MODE 3: alpha*(g_agg @ Wd + bd) + (1-alpha)*xres   -> out_ext
// ---------------------------------------------------------------------------
#define BM 64
#define KC 32
#define ASTR 40   // bf16 row stride: conflict-free frag loads

__device__ __forceinline__ void mma_bf16(float* d, const uint32_t* a,
                                         const uint32_t* b) {
    asm volatile(
        "mma.sync.aligned.m16n8k16.row.col.f32.bf16.bf16.f32 "
        "{%0,%1,%2,%3}, {%4,%5,%6,%7}, {%8,%9}, {%0,%1,%2,%3};"
        : "+f"(d[0]), "+f"(d[1]), "+f"(d[2]), "+f"(d[3])
        : "r"(a[0]), "r"(a[1]), "r"(a[2]), "r"(a[3]), "r"(b[0]), "r"(b[1]));
}

__device__ __forceinline__ uint32_t bf2_hi(float x, float y) {
    __nv_bfloat162 h = __floats2bfloat162_rn(x, y);
    return *(uint32_t*)&h;
}

template <int MODE>
__global__ __launch_bounds__(256) void gemm_kernel(
    const float* __restrict__ selfA,   // MODE 1: x
    const float* __restrict__ Wa,      // W_l (or Wd)
    const float* __restrict__ Wb,      // W_r (MODE 1/2)
    const float* __restrict__ bias,
    const float* __restrict__ xres,    // MODE 3
    const float* __restrict__ alpha_p, // MODE 3
    float* __restrict__ out_ext,       // MODE 3
    int n)
{
    __shared__ __nv_bfloat16 Ahi[BM][ASTR];
    __shared__ __nv_bfloat16 Alo[BM][ASTR];
    __shared__ __nv_bfloat16 Bhi[128][ASTR];
    __shared__ __nv_bfloat16 Blo[128][ASTR];
    __shared__ float s_bias[128];
    __shared__ float s_deg[BM];

    int t = threadIdx.x;
    int lane = t & 31;
    int w = t >> 5;
    int wm = w >> 2;
    int wn = w & 3;
    int block_row = blockIdx.x * BM;

    if (t < 128) s_bias[t] = bias[t];
    if (t < BM && MODE != 3) {
        int r = block_row + t;
        float dg = (r < n) ? g_deg[r] : 1.0f;
        s_deg[t] = 1.0f / fmaxf(dg, 1.0f);
    }

    const int NCH = (MODE == 3) ? 4 : 8;

    // ---- per-chunk global loaders (into registers) ----
    int arow = t >> 2;                 // 0..63
    int aks = (t & 3) * 8;             // 0,8,16,24
    int bnn = t >> 1;                  // 0..127
    int bks = (t & 1) * 16;            // 0,16

    auto loadA = [&](int c, float4& v0, float4& v1) {
        const float* Asrc;
        if (MODE == 3) Asrc = g_agg;
        else if (c < 4) Asrc = (MODE == 1) ? g_agg : g_agg2;
        else Asrc = (MODE == 1) ? selfA : g_h1;
        int kofs = (MODE == 3) ? c * KC : (c & 3) * KC;
        v0 = make_float4(0.f, 0.f, 0.f, 0.f);
        v1 = v0;
        int grow = block_row + arow;
        if (grow < n) {
            const float* p = Asrc + (size_t)grow * CH + kofs + aks;
            v0 = *(const float4*)p;
            v1 = *(const float4*)(p + 4);
        }
    };
    auto loadB = [&](int c, float* vb) {
        const float* Bsrc = (MODE == 3) ? Wa : ((c < 4) ? Wa : Wb);
        int kofs = (MODE == 3) ? c * KC : (c & 3) * KC;
        #pragma unroll
        for (int j = 0; j < 16; j++)
            vb[j] = Bsrc[(size_t)(kofs + bks + j) * CH + bnn];
    };
    auto stageA = [&](int c, float4 v0, float4 v1) {
        if (MODE != 3 && c < 4) {
            float sc = s_deg[arow];
            v0.x *= sc; v0.y *= sc; v0.z *= sc; v0.w *= sc;
            v1.x *= sc; v1.y *= sc; v1.z *= sc; v1.w *= sc;
        }
        uint4 hi, lo;
        hi.x = bf2_hi(v0.x, v0.y);  hi.y = bf2_hi(v0.z, v0.w);
        hi.z = bf2_hi(v1.x, v1.y);  hi.w = bf2_hi(v1.z, v1.w);
        float2 h0 = __bfloat1622float2(*(__nv_bfloat162*)&hi.x);
        float2 h1 = __bfloat1622float2(*(__nv_bfloat162*)&hi.y);
        float2 h2 = __bfloat1622float2(*(__nv_bfloat162*)&hi.z);
        float2 h3 = __bfloat1622float2(*(__nv_bfloat162*)&hi.w);
        lo.x = bf2_hi(v0.x - h0.x, v0.y - h0.y);
        lo.y = bf2_hi(v0.z - h1.x, v0.w - h1.y);
        lo.z = bf2_hi(v1.x - h2.x, v1.y - h2.y);
        lo.w = bf2_hi(v1.z - h3.x, v1.w - h3.y);
        *(uint4*)&Ahi[arow][aks] = hi;
        *(uint4*)&Alo[arow][aks] = lo;
    };
    auto stageB = [&](const float* vb) {
        uint32_t hw[8], lw[8];
        #pragma unroll
        for (int j = 0; j < 8; j++) {
            hw[j] = bf2_hi(vb[2 * j], vb[2 * j + 1]);
            float2 hf = __bfloat1622float2(*(__nv_bfloat162*)&hw[j]);
            lw[j] = bf2_hi(vb[2 * j] - hf.x, vb[2 * j + 1] - hf.y);
        }
        *(uint4*)&Bhi[bnn][bks]     = make_uint4(hw[0], hw[1], hw[2], hw[3]);
        *(uint4*)&Bhi[bnn][bks + 8] = make_uint4(hw[4], hw[5], hw[6], hw[7]);
        *(uint4*)&Blo[bnn][bks]     = make_uint4(lw[0], lw[1], lw[2], lw[3]);
        *(uint4*)&Blo[bnn][bks + 8] = make_uint4(lw[4], lw[5], lw[6], lw[7]);
    };

    float acc[2][4][4];
    #pragma unroll
    for (int mi = 0; mi < 2; mi++)
        #pragma unroll
        for (int nj = 0; nj < 4; nj++)
            #pragma unroll
            for (int q = 0; q < 4; q++) acc[mi][nj][q] = 0.f;

    // ---- prologue: stage chunk 0 ----
    float4 pa0, pa1;
    float pb[16];
    loadA(0, pa0, pa1);
    loadB(0, pb);
    __syncthreads();           // s_deg/s_bias visible
    stageA(0, pa0, pa1);
    stageB(pb);
    __syncthreads();

    #pragma unroll 1
    for (int c = 0; c < NCH; c++) {
        // prefetch next chunk while mma consumes current smem
        if (c + 1 < NCH) {
            loadA(c + 1, pa0, pa1);
            loadB(c + 1, pb);
        }

        // ---- mma: 2 k16-steps, 3 passes each (identical to proven R8) ----
        #pragma unroll
        for (int kk = 0; kk < KC; kk += 16) {
            int kw = kk + (lane & 3) * 2;
            int rr = wm * 32 + (lane >> 2);
            uint32_t a_hi[2][4], a_lo[2][4], b_hi[4][2], b_lo[4][2];
            #pragma unroll
            for (int mi = 0; mi < 2; mi++) {
                int r = rr + mi * 16;
                a_hi[mi][0] = *(uint32_t*)&Ahi[r][kw];
                a_hi[mi][1] = *(uint32_t*)&Ahi[r + 8][kw];
                a_hi[mi][2] = *(uint32_t*)&Ahi[r][kw + 8];
                a_hi[mi][3] = *(uint32_t*)&Ahi[r + 8][kw + 8];
                a_lo[mi][0] = *(uint32_t*)&Alo[r][kw];
                a_lo[mi][1] = *(uint32_t*)&Alo[r + 8][kw];
                a_lo[mi][2] = *(uint32_t*)&Alo[r][kw + 8];
                a_lo[mi][3] = *(uint32_t*)&Alo[r + 8][kw + 8];
            }
            #pragma unroll
            for (int nj = 0; nj < 4; nj++) {
                int cn = wn * 32 + nj * 8 + (lane >> 2);
                b_hi[nj][0] = *(uint32_t*)&Bhi[cn][kw];
                b_hi[nj][1] = *(uint32_t*)&Bhi[cn][kw + 8];
                b_lo[nj][0] = *(uint32_t*)&Blo[cn][kw];
                b_lo[nj][1] = *(uint32_t*)&Blo[cn][kw + 8];
            }
            #pragma unroll
            for (int mi = 0; mi < 2; mi++)
                #pragma unroll
                for (int nj = 0; nj < 4; nj++) {
                    mma_bf16(acc[mi][nj], a_hi[mi], b_hi[nj]);
                    mma_bf16(acc[mi][nj], a_hi[mi], b_lo[nj]);
                    mma_bf16(acc[mi][nj], a_lo[mi], b_hi[nj]);
                }
        }

        if (c + 1 < NCH) {
            __syncthreads();           // all warps done reading smem
            stageA(c + 1, pa0, pa1);   // convert + STS next chunk
            stageB(pb);
            __syncthreads();
        }
    }

    // ---- epilogue ----
    float alpha = 0.f, one_m = 0.f;
    if (MODE == 3) { alpha = *alpha_p; one_m = 1.0f - alpha; }
    float* outp = (MODE == 1) ? g_h1 : ((MODE == 2) ? g_agg : out_ext);

    #pragma unroll
    for (int mi = 0; mi < 2; mi++) {
        #pragma unroll
        for (int part = 0; part < 2; part++) {
            int grow = block_row + wm * 32 + mi * 16 + part * 8 + (lane >> 2);
            if (grow < n) {
                #pragma unroll
                for (int nj = 0; nj < 4; nj++) {
                    int gcol = wn * 32 + nj * 8 + (lane & 3) * 2;
                    float v0 = acc[mi][nj][part * 2 + 0] + s_bias[gcol];
                    float v1 = acc[mi][nj][part * 2 + 1] + s_bias[gcol + 1];
                    float2 o;
                    if (MODE == 3) {
                        float2 xv = *(const float2*)(xres + (size_t)grow * CH + gcol);
                        o.x = alpha * v0 + one_m * xv.x;
                        o.y = alpha * v1 + one_m * xv.y;
                    } else {
                        o.x = fmaxf(v0, 0.f);
                        o.y = fmaxf(v1, 0.f);
                    }
                    *(float2*)(outp + (size_t)grow * CH + gcol) = o;
                }
            }
        }
    }
}

// ---------------------------------------------------------------------------
extern "C" void kernel_launch(void* const* d_in, const int* in_sizes, int n_in,
                              void* d_out, int out_size) {
    const float* x     = (const float*)d_in[0];
    const void*  edge  = d_in[1];
    const float* W1_l  = (const float*)d_in[2];
    const float* b1    = (const float*)d_in[3];
    const float* W1_r  = (const float*)d_in[4];
    const float* W2_l  = (const float*)d_in[5];
    const float* b2    = (const float*)d_in[6];
    const float* W2_r  = (const float*)d_in[7];
    const float* Wd    = (const float*)d_in[8];
    const float* bd    = (const float*)d_in[9];
    const float* alpha = (const float*)d_in[10];
    float* out = (float*)d_out;

    int n = in_sizes[0] / CH;            // 50000
    int E = in_sizes[1] / 2;             // 640000

    int clear_blocks = (N_NODES * CH / 4 + 255) / 256;
    int scat_blocks  = (E + 7) / 8;
    int gemm_blocks  = (n + BM - 1) / BM;   // 782

    detect_kernel<<<1, 256>>>((const unsigned*)edge);
    clear_kernel<<<clear_blocks, 256>>>();   // g_agg, g_agg2, g_deg

    // Layer 1
    scatter_kernel<0><<<scat_blocks, 256>>>(x, edge, E);
    gemm_kernel<1><<<gemm_blocks, 256>>>(x, W1_l, W1_r, b1,
                                         nullptr, nullptr, nullptr, n);
    // Layer 2
    scatter_kernel<1><<<scat_blocks, 256>>>(nullptr, edge, E);
    gemm_kernel<2><<<gemm_blocks, 256>>>(nullptr, W2_l, W2_r, b2,
                                         nullptr, nullptr, nullptr, n);
    // Decoder + residual
    gemm_kernel<3><<<gemm_blocks, 256>>>(nullptr, Wd, nullptr, bd,
                                         x, alpha, out, n);
}

// round 11
// speedup vs baseline: 1.7458x; 1.5356x over previous
#include <cuda_runtime.h>
#include <cuda_bf16.h>
#include <cstdint>

#define N_NODES 50000
#define EMAX    1000000
#define CH      128

// Scratch (device globals -- no allocation allowed)
__device__ __align__(16) float g_agg[(size_t)N_NODES * CH];
__device__ __align__(16) float g_h1[(size_t)N_NODES * CH];
__device__ int g_cnt[N_NODES];
__device__ int g_row[N_NODES + 1];
__device__ int g_cursor[N_NODES];
__device__ int g_bsum[64];
__device__ int g_boff[64];
__device__ int g_col[EMAX];
__device__ int g_is64;

// ---------------------------------------------------------------------------
// edge index read (int32 vs int64 runtime-detected)
// ---------------------------------------------------------------------------
__device__ __forceinline__ int edge_at(const void* e, int i) {
    return g_is64 ? (int)((const long long*)e)[i] : ((const int*)e)[i];
}

__global__ void detect_kernel(const unsigned* __restrict__ e) {
    __shared__ unsigned red[256];
    unsigned acc = 0;
    int t = threadIdx.x;
    #pragma unroll
    for (int j = 0; j < 8; j++) acc |= e[(t * 8 + j) * 2 + 1];
    red[t] = acc;
    __syncthreads();
    for (int s = 128; s > 0; s >>= 1) {
        if (t < s) red[t] |= red[t + s];
        __syncthreads();
    }
    if (t == 0) g_is64 = (red[0] == 0) ? 1 : 0;
}

// ---------------------------------------------------------------------------
// CSR build: histogram -> scan -> fill
// ---------------------------------------------------------------------------
__global__ void clear_cnt_kernel(int n) {
    int i = blockIdx.x * blockDim.x + threadIdx.x;
    if (i < n) g_cnt[i] = 0;
}

__global__ void hist_kernel(const void* __restrict__ edge, int E, int n) {
    int i = blockIdx.x * blockDim.x + threadIdx.x;
    if (i >= E) return;
    int d = edge_at(edge, E + i);
    if ((unsigned)d < (unsigned)n) atomicAdd(&g_cnt[d], 1);
}

__global__ void scan1_kernel(int n) {
    __shared__ int sh[1024];
    int t = threadIdx.x;
    int idx = blockIdx.x * 1024 + t;
    int v = (idx < n) ? g_cnt[idx] : 0;
    sh[t] = v;
    __syncthreads();
    #pragma unroll
    for (int off = 1; off < 1024; off <<= 1) {
        int add = (t >= off) ? sh[t - off] : 0;
        __syncthreads();
        sh[t] += add;
        __syncthreads();
    }
    if (idx < n) g_row[idx] = sh[t] - v;        // exclusive within block
    if (t == 1023) g_bsum[blockIdx.x] = sh[1023];
}

__global__ void scan2_kernel(int nb) {
    __shared__ int sh[64];
    int t = threadIdx.x;
    sh[t] = (t < nb) ? g_bsum[t] : 0;
    __syncthreads();
    if (t == 0) {
        int run = 0;
        for (int i = 0; i < nb; i++) {
            g_boff[i] = run;
            run += sh[i];
        }
    }
}

__global__ void scan3_kernel(int n, int E) {
    int idx = blockIdx.x * 1024 + threadIdx.x;
    if (idx < n) {
        g_row[idx] += g_boff[blockIdx.x];
        g_cursor[idx] = 0;
    }
    if (idx == 0) g_row[n] = E;
}

__global__ void fill_kernel(const void* __restrict__ edge, int E, int n) {
    int i = blockIdx.x * blockDim.x + threadIdx.x;
    if (i >= E) return;
    int s = edge_at(edge, i);
    int d = edge_at(edge, E + i);
    if ((unsigned)d >= (unsigned)n) return;
    if ((unsigned)s >= (unsigned)n) s = 0;      // never happens on valid data
    int pos = g_row[d] + atomicAdd(&g_cursor[d], 1);
    g_col[pos] = s;
}

// ---------------------------------------------------------------------------
// aggregate: one warp per destination row, pure gather, mean folded in.
// SRC 0: feat = x (param). SRC 1: feat = g_h1. Output: g_agg (pre-scaled).
// ---------------------------------------------------------------------------
template <int SRC>
__global__ void aggregate_kernel(const float* __restrict__ feat_ext, int n) {
    int row = (blockIdx.x * blockDim.x + threadIdx.x) >> 5;
    int lane = threadIdx.x & 31;
    if (row >= n) return;

    const float* __restrict__ feat = (SRC == 0) ? feat_ext : g_h1;

    int base = g_row[row];
    int end  = g_row[row + 1];
    int deg  = end - base;

    float a0 = 0.f, a1 = 0.f, a2 = 0.f, a3 = 0.f;
    int j = base;
    // 2-deep manual unroll for memory-level parallelism
    for (; j + 1 < end; j += 2) {
        int s0 = g_col[j];
        int s1 = g_col[j + 1];
        float4 v0 = *(const float4*)(feat + (size_t)s0 * CH + lane * 4);
        float4 v1 = *(const float4*)(feat + (size_t)s1 * CH + lane * 4);
        a0 += v0.x + v1.x;
        a1 += v0.y + v1.y;
        a2 += v0.z + v1.z;
        a3 += v0.w + v1.w;
    }
    if (j < end) {
        int s0 = g_col[j];
        float4 v0 = *(const float4*)(feat + (size_t)s0 * CH + lane * 4);
        a0 += v0.x; a1 += v0.y; a2 += v0.z; a3 += v0.w;
    }

    float sc = 1.0f / fmaxf((float)deg, 1.0f);
    float4 o = make_float4(a0 * sc, a1 * sc, a2 * sc, a3 * sc);
    *(float4*)(g_agg + (size_t)row * CH + lane * 4) = o;
}

// ---------------------------------------------------------------------------
// GEMM via mma.sync m16n8k16 bf16 (HMMA), bf16x3 split (proven R8 math).
// BM=64, BN=128, KC=32. 8 warps in 2(M) x 4(N); warp tile 32x32.
// g_agg is pre-scaled by 1/deg (mean folded into aggregate).
// MODE 1: relu( [agg | x ] @ [W1_l;W1_r] + b1 ) -> g_h1     (K=256)
// MODE 2: relu( [agg | h1] @ [W2_l;W2_r] + b2 ) -> g_agg (h2)
// MODE 3: alpha*(g_agg @ Wd + bd) + (1-alpha)*xres -> out_ext (K=128)
// ---------------------------------------------------------------------------
#define BM 64
#define KC 32
#define ASTR 40

__device__ __forceinline__ void mma_bf16(float* d, const uint32_t* a,
                                         const uint32_t* b) {
    asm volatile(
        "mma.sync.aligned.m16n8k16.row.col.f32.bf16.bf16.f32 "
        "{%0,%1,%2,%3}, {%4,%5,%6,%7}, {%8,%9}, {%0,%1,%2,%3};"
        : "+f"(d[0]), "+f"(d[1]), "+f"(d[2]), "+f"(d[3])
        : "r"(a[0]), "r"(a[1]), "r"(a[2]), "r"(a[3]), "r"(b[0]), "r"(b[1]));
}

__device__ __forceinline__ uint32_t bf2_hi(float x, float y) {
    __nv_bfloat162 h = __floats2bfloat162_rn(x, y);
    return *(uint32_t*)&h;
}

template <int MODE>
__global__ __launch_bounds__(256) void gemm_kernel(
    const float* __restrict__ selfA,   // MODE 1: x
    const float* __restrict__ Wa,      // W_l (or Wd)
    const float* __restrict__ Wb,      // W_r (MODE 1/2)
    const float* __restrict__ bias,
    const float* __restrict__ xres,    // MODE 3
    const float* __restrict__ alpha_p, // MODE 3
    float* __restrict__ out_ext,       // MODE 3
    int n)
{
    __shared__ __nv_bfloat16 Ahi[BM][ASTR];
    __shared__ __nv_bfloat16 Alo[BM][ASTR];
    __shared__ __nv_bfloat16 Bhi[128][ASTR];
    __shared__ __nv_bfloat16 Blo[128][ASTR];
    __shared__ float s_bias[128];

    int t = threadIdx.x;
    int lane = t & 31;
    int w = t >> 5;
    int wm = w >> 2;
    int wn = w & 3;
    int block_row = blockIdx.x * BM;

    if (t < 128) s_bias[t] = bias[t];

    float acc[2][4][4];
    #pragma unroll
    for (int mi = 0; mi < 2; mi++)
        #pragma unroll
        for (int nj = 0; nj < 4; nj++)
            #pragma unroll
            for (int q = 0; q < 4; q++) acc[mi][nj][q] = 0.f;

    const int NCH = (MODE == 3) ? 4 : 8;

    #pragma unroll 1
    for (int c = 0; c < NCH; c++) {
        const float* Asrc;
        const float* Bsrc;
        int kofs;
        if (MODE == 3) { Asrc = g_agg; Bsrc = Wa; kofs = c * KC; }
        else {
            kofs = (c & 3) * KC;
            Asrc = (c < 4) ? g_agg : ((MODE == 1) ? selfA : g_h1);
            Bsrc = (c < 4) ? Wa : Wb;
        }
        __syncthreads();   // previous chunk's mma reads done before restage

        // ---- stage A: 64 rows x 32 k, fp32 -> bf16 hi/lo ----
        {
            int row = t >> 2;            // 0..63
            int ks = (t & 3) * 8;        // 0,8,16,24
            int grow = block_row + row;
            float4 v0 = make_float4(0.f, 0.f, 0.f, 0.f);
            float4 v1 = v0;
            if (grow < n) {
                const float* p = Asrc + (size_t)grow * CH + kofs + ks;
                v0 = *(const float4*)p;
                v1 = *(const float4*)(p + 4);
            }
            uint4 hi, lo;
            hi.x = bf2_hi(v0.x, v0.y);  hi.y = bf2_hi(v0.z, v0.w);
            hi.z = bf2_hi(v1.x, v1.y);  hi.w = bf2_hi(v1.z, v1.w);
            float2 h0 = __bfloat1622float2(*(__nv_bfloat162*)&hi.x);
            float2 h1 = __bfloat1622float2(*(__nv_bfloat162*)&hi.y);
            float2 h2 = __bfloat1622float2(*(__nv_bfloat162*)&hi.z);
            float2 h3 = __bfloat1622float2(*(__nv_bfloat162*)&hi.w);
            lo.x = bf2_hi(v0.x - h0.x, v0.y - h0.y);
            lo.y = bf2_hi(v0.z - h1.x, v0.w - h1.y);
            lo.z = bf2_hi(v1.x - h2.x, v1.y - h2.y);
            lo.w = bf2_hi(v1.z - h3.x, v1.w - h3.y);
            *(uint4*)&Ahi[row][ks] = hi;
            *(uint4*)&Alo[row][ks] = lo;
        }

        // ---- stage B (transposed): Bs[n][k] = W[kofs+k][n], hi/lo ----
        {
            int nn = t >> 1;             // 0..127
            int ks = (t & 1) * 16;       // 0,16
            uint32_t hw[8], lw[8];
            #pragma unroll
            for (int j = 0; j < 8; j++) {
                float va = Bsrc[(size_t)(kofs + ks + 2 * j) * CH + nn];
                float vb = Bsrc[(size_t)(kofs + ks + 2 * j + 1) * CH + nn];
                hw[j] = bf2_hi(va, vb);
                float2 hf = __bfloat1622float2(*(__nv_bfloat162*)&hw[j]);
                lw[j] = bf2_hi(va - hf.x, vb - hf.y);
            }
            *(uint4*)&Bhi[nn][ks]     = make_uint4(hw[0], hw[1], hw[2], hw[3]);
            *(uint4*)&Bhi[nn][ks + 8] = make_uint4(hw[4], hw[5], hw[6], hw[7]);
            *(uint4*)&Blo[nn][ks]     = make_uint4(lw[0], lw[1], lw[2], lw[3]);
            *(uint4*)&Blo[nn][ks + 8] = make_uint4(lw[4], lw[5], lw[6], lw[7]);
        }
        __syncthreads();

        // ---- mma: 2 k16-steps, 3 passes each ----
        #pragma unroll
        for (int kk = 0; kk < KC; kk += 16) {
            int kw = kk + (lane & 3) * 2;
            int rr = wm * 32 + (lane >> 2);
            uint32_t a_hi[2][4], a_lo[2][4], b_hi[4][2], b_lo[4][2];
            #pragma unroll
            for (int mi = 0; mi < 2; mi++) {
                int r = rr + mi * 16;
                a_hi[mi][0] = *(uint32_t*)&Ahi[r][kw];
                a_hi[mi][1] = *(uint32_t*)&Ahi[r + 8][kw];
                a_hi[mi][2] = *(uint32_t*)&Ahi[r][kw + 8];
                a_hi[mi][3] = *(uint32_t*)&Ahi[r + 8][kw + 8];
                a_lo[mi][0] = *(uint32_t*)&Alo[r][kw];
                a_lo[mi][1] = *(uint32_t*)&Alo[r + 8][kw];
                a_lo[mi][2] = *(uint32_t*)&Alo[r][kw + 8];
                a_lo[mi][3] = *(uint32_t*)&Alo[r + 8][kw + 8];
            }
            #pragma unroll
            for (int nj = 0; nj < 4; nj++) {
                int cn = wn * 32 + nj * 8 + (lane >> 2);
                b_hi[nj][0] = *(uint32_t*)&Bhi[cn][kw];
                b_hi[nj][1] = *(uint32_t*)&Bhi[cn][kw + 8];
                b_lo[nj][0] = *(uint32_t*)&Blo[cn][kw];
                b_lo[nj][1] = *(uint32_t*)&Blo[cn][kw + 8];
            }
            #pragma unroll
            for (int mi = 0; mi < 2; mi++)
                #pragma unroll
                for (int nj = 0; nj < 4; nj++) {
                    mma_bf16(acc[mi][nj], a_hi[mi], b_hi[nj]);
                    mma_bf16(acc[mi][nj], a_hi[mi], b_lo[nj]);
                    mma_bf16(acc[mi][nj], a_lo[mi], b_hi[nj]);
                }
        }
    }

    // ---- epilogue ----
    float alpha = 0.f, one_m = 0.f;
    if (MODE == 3) { alpha = *alpha_p; one_m = 1.0f - alpha; }
    float* outp = (MODE == 1) ? g_h1 : ((MODE == 2) ? g_agg : out_ext);

    #pragma unroll
    for (int mi = 0; mi < 2; mi++) {
        #pragma unroll
        for (int part = 0; part < 2; part++) {
            int grow = block_row + wm * 32 + mi * 16 + part * 8 + (lane >> 2);
            if (grow < n) {
                #pragma unroll
                for (int nj = 0; nj < 4; nj++) {
                    int gcol = wn * 32 + nj * 8 + (lane & 3) * 2;
                    float v0 = acc[mi][nj][part * 2 + 0] + s_bias[gcol];
                    float v1 = acc[mi][nj][part * 2 + 1] + s_bias[gcol + 1];
                    float2 o;
                    if (MODE == 3) {
                        float2 xv = *(const float2*)(xres + (size_t)grow * CH + gcol);
                        o.x = alpha * v0 + one_m * xv.x;
                        o.y = alpha * v1 + one_m * xv.y;
                    } else {
                        o.x = fmaxf(v0, 0.f);
                        o.y = fmaxf(v1, 0.f);
                    }
                    *(float2*)(outp + (size_t)grow * CH + gcol) = o;
                }
            }
        }
    }
}

// ---------------------------------------------------------------------------
extern "C" void kernel_launch(void* const* d_in, const int* in_sizes, int n_in,
                              void* d_out, int out_size) {
    const float* x     = (const float*)d_in[0];
    const void*  edge  = d_in[1];
    const float* W1_l  = (const float*)d_in[2];
    const float* b1    = (const float*)d_in[3];
    const float* W1_r  = (const float*)d_in[4];
    const float* W2_l  = (const float*)d_in[5];
    const float* b2    = (const float*)d_in[6];
    const float* W2_r  = (const float*)d_in[7];
    const float* Wd    = (const float*)d_in[8];
    const float* bd    = (const float*)d_in[9];
    const float* alpha = (const float*)d_in[10];
    float* out = (float*)d_out;

    int n = in_sizes[0] / CH;            // 50000
    int E = in_sizes[1] / 2;             // 640000
    if (E > EMAX) E = EMAX;

    int eb   = (E + 255) / 256;          // 2500
    int nb   = (n + 255) / 256;
    int sb   = (n + 1023) / 1024;        // 49 scan blocks
    int ab   = (n * 32 + 255) / 256;     // aggregate: warp per row
    int gb   = (n + BM - 1) / BM;        // 782

    // CSR build (once, serves both layers)
    detect_kernel<<<1, 256>>>((const unsigned*)edge);
    clear_cnt_kernel<<<nb, 256>>>(n);
    hist_kernel<<<eb, 256>>>(edge, E, n);
    scan1_kernel<<<sb, 1024>>>(n);
    scan2_kernel<<<1, 64>>>(sb);
    scan3_kernel<<<sb, 1024>>>(n, E);
    fill_kernel<<<eb, 256>>>(edge, E, n);

    // Layer 1
    aggregate_kernel<0><<<ab, 256>>>(x, n);
    gemm_kernel<1><<<gb, 256>>>(x, W1_l, W1_r, b1,
                                nullptr, nullptr, nullptr, n);
    // Layer 2
    aggregate_kernel<1><<<ab, 256>>>(nullptr, n);
    gemm_kernel<2><<<gb, 256>>>(nullptr, W2_l, W2_r, b2,
                                nullptr, nullptr, nullptr, n);
    // Decoder + residual
    gemm_kernel<3><<<gb, 256>>>(nullptr, Wd, nullptr, bd,
                                x, alpha, out, n);
}